// round 13
// baseline (speedup 1.0000x reference)
#include <cuda_runtime.h>
#include <cstdint>

// ---------------------------------------------------------------------------
// Shapes
// ---------------------------------------------------------------------------
#define BT   12
#define CF   1024
#define CQ   128
#define NTOK 2401
#define NP   2432
#define HF   49

// ---------------------------------------------------------------------------
// Scratch
// ---------------------------------------------------------------------------
__device__ float g_X  [(size_t)BT * CF * NP];   // residual [bt][c][n]
__device__ float g_XTh[(size_t)BT * NP * CF];   // XT hi
__device__ float g_XTl[(size_t)BT * NP * CF];   // XT lo
__device__ float g_Wvh[(size_t)CF * CF];        // Wv rounded
__device__ float g_Wqh[(size_t)CQ * CF];
__device__ float g_Wql[(size_t)CQ * CF];
__device__ float g_Wkh[(size_t)CQ * CF];
__device__ float g_Wkl[(size_t)CQ * CF];
__device__ float g_QTh[(size_t)BT * NP * CQ];
__device__ float g_QTl[(size_t)BT * NP * CQ];
__device__ float g_KTh[(size_t)BT * NP * CQ];
__device__ float g_KTl[(size_t)BT * NP * CQ];
__device__ float g_V  [(size_t)BT * CF * NP];   // v rounded (incl bias)
__device__ float g_ATT[(size_t)BT * NP * NP];   // raw scores -> rounded probs

__device__ __forceinline__ uint32_t f2tf(float f) {
    uint32_t u; asm("cvt.rna.tf32.f32 %0, %1;" : "=r"(u) : "f"(f)); return u;
}
__device__ __forceinline__ float tf32f(float f) { return __uint_as_float(f2tf(f)); }
__device__ __forceinline__ uint32_t smem_u32(const void* p) {
    uint32_t a;
    asm("{ .reg .u64 t; cvta.to.shared.u64 t, %1; cvt.u32.u64 %0, t; }" : "=r"(a) : "l"(p));
    return a;
}

__device__ __forceinline__ void mma_tf32(float c[4], const uint32_t a[4], const uint32_t b[2]) {
    asm volatile(
        "mma.sync.aligned.m16n8k8.row.col.f32.tf32.tf32.f32 "
        "{%0,%1,%2,%3}, {%4,%5,%6,%7}, {%8,%9}, {%0,%1,%2,%3};"
        : "+f"(c[0]), "+f"(c[1]), "+f"(c[2]), "+f"(c[3])
        : "r"(a[0]), "r"(a[1]), "r"(a[2]), "r"(a[3]), "r"(b[0]), "r"(b[1]));
}

#define CP_ASYNC16(dst_u32, src_ptr) \
    asm volatile("cp.async.cg.shared.global [%0], [%1], 16;" :: "r"(dst_u32), "l"(src_ptr) : "memory")
#define CP_COMMIT() asm volatile("cp.async.commit_group;" ::: "memory")
#define CP_WAIT0()  asm volatile("cp.async.wait_group 0;" ::: "memory")
#define CP_WAIT1()  asm volatile("cp.async.wait_group 1;" ::: "memory")

// ---------------------------------------------------------------------------
// 1a) residual X[bt][c][n]
// ---------------------------------------------------------------------------
__global__ void build_x_kernel(const float* __restrict__ img,
                               const float* __restrict__ tac) {
    int n = blockIdx.x * 256 + threadIdx.x;
    int c = blockIdx.y, bt = blockIdx.z;
    if (n >= NP) return;
    float v = 0.0f;
    if (n < NTOK) {
        int i = n / HF, j = n % HF;
        v = (c < 512)
            ? tac[(((size_t)bt * 512 + c) * 7 + (i / 7)) * 7 + (j / 7)]
            : img[(((size_t)bt * 512 + (c - 512)) * 7 + (i % 7)) * 7 + (j % 7)];
    }
    g_X[((size_t)bt * CF + c) * NP + n] = v;
}

// ---------------------------------------------------------------------------
// 1b) XT hi/lo (zero rows for n >= NTOK)
// ---------------------------------------------------------------------------
__global__ void build_xt_kernel(const float* __restrict__ img,
                                const float* __restrict__ tac) {
    int c = blockIdx.x * 256 + threadIdx.x;
    int n = blockIdx.y, bt = blockIdx.z;
    if (c >= CF) return;
    float v = 0.0f;
    if (n < NTOK) {
        int i = n / HF, j = n % HF;
        v = (c < 512)
            ? tac[(((size_t)bt * 512 + c) * 7 + (i / 7)) * 7 + (j / 7)]
            : img[(((size_t)bt * 512 + (c - 512)) * 7 + (i % 7)) * 7 + (j % 7)];
    }
    float h = tf32f(v);
    size_t base = ((size_t)bt * NP + n) * CF + c;
    g_XTh[base] = h;
    g_XTl[base] = tf32f(v - h);
}

// ---------------------------------------------------------------------------
// 1c) weight prep
// ---------------------------------------------------------------------------
__global__ void prep_round_kernel(const float* __restrict__ src,
                                  float* __restrict__ dst, int n) {
    int i = blockIdx.x * 256 + threadIdx.x;
    if (i < n) dst[i] = tf32f(src[i]);
}
__global__ void prep_split_kernel(const float* __restrict__ src,
                                  float* __restrict__ dh, float* __restrict__ dl, int n) {
    int i = blockIdx.x * 256 + threadIdx.x;
    if (i >= n) return;
    float v = src[i];
    float h = tf32f(v);
    dh[i] = h;
    dl[i] = tf32f(v - h);
}

// ---------------------------------------------------------------------------
// 2) row softmax, writes tf32-rounded probs, zeroes padding
// ---------------------------------------------------------------------------
__global__ __launch_bounds__(256)
void softmax_kernel() {
    __shared__ float row[NTOK];
    __shared__ float red[256];
    const int n = blockIdx.x, bt = blockIdx.y;
    float* base = g_ATT + ((size_t)bt * NP + n) * NP;
    const int t = threadIdx.x;

    float mx = -1e30f;
    for (int m = t; m < NTOK; m += 256) { float v = base[m]; row[m] = v; mx = fmaxf(mx, v); }
    red[t] = mx; __syncthreads();
    for (int s = 128; s > 0; s >>= 1) { if (t < s) red[t] = fmaxf(red[t], red[t + s]); __syncthreads(); }
    mx = red[0]; __syncthreads();

    float sum = 0.0f;
    for (int m = t; m < NTOK; m += 256) { float e = __expf(row[m] - mx); row[m] = e; sum += e; }
    red[t] = sum; __syncthreads();
    for (int s = 128; s > 0; s >>= 1) { if (t < s) red[t] += red[t + s]; __syncthreads(); }
    float inv = 1.0f / red[0];

    for (int m = t; m < NTOK; m += 256) base[m] = tf32f(row[m] * inv);
    for (int m = NTOK + t; m < NP; m += 256) base[m] = 0.0f;
}

// ---------------------------------------------------------------------------
// Tiling constants
// ---------------------------------------------------------------------------
#define LDS_S 36
#define TILEW (128 * LDS_S)            // SPLIT1: words per 128x32 tile
#define SMEM_T (4 * TILEW * 4)         // 73728 B double buffer

#define S3 20                          // SPLIT3 pre-split: stride for 16-float rows
#define T3 (128 * S3)                  // words per 128x16 tile
#define STG3 (4 * T3)                  // Ah, Al, Bh, Bl per stage
#define SMEM_3 (2 * STG3 * 4)          // 81920 B double buffer

// ---------------------------------------------------------------------------
// 3) SPLIT=1 GEMM on PRE-ROUNDED operands (R12 form, unchanged).
//    EPI 0: C = tf32f(acc + bias[row])   EPI 1: C = gamma*acc + X, col<NTOK
// ---------------------------------------------------------------------------
template <int EPI>
__global__ __launch_bounds__(256, 2)
void gemm_async_kernel(const float* __restrict__ A, int lda, size_t strideA,
                       const float* __restrict__ B, int ldb, size_t strideB,
                       int K,
                       const float* __restrict__ bias,
                       const float* __restrict__ gamma,
                       const float* __restrict__ Xres,
                       float* __restrict__ C, int ldc, size_t strideC) {
    extern __shared__ uint32_t sm[];
    const uint32_t smem_base = smem_u32(sm);

    const int bt = blockIdx.z;
    const int m0 = blockIdx.x * 128;
    const int n0 = blockIdx.y * 128;
    const float* Ab = A + (size_t)bt * strideA + (size_t)m0 * lda;
    const float* Bb = B + (size_t)bt * strideB + (size_t)n0 * ldb;

    const int t = threadIdx.x;
    const int wid = t >> 5, lane = t & 31;
    const int warp_m = wid & 1, warp_n = wid >> 1;
    const int l4 = lane >> 2, lm = lane & 3;

    const int prow = t >> 1;
    const int pcol = (t & 1) * 16;
    const float* aRow = Ab + (size_t)prow * lda + pcol;
    const float* bRow = Bb + (size_t)prow * ldb + pcol;
    const uint32_t sA0 = smem_base + (prow * LDS_S + pcol) * 4;
    const uint32_t sB0 = sA0 + TILEW * 4;

    float acc[4][4][4];
    #pragma unroll
    for (int mi = 0; mi < 4; mi++)
        #pragma unroll
        for (int ni = 0; ni < 4; ni++)
            #pragma unroll
            for (int r = 0; r < 4; r++) acc[mi][ni][r] = 0.0f;

    const int NCH = K / 32;

    #pragma unroll
    for (int q = 0; q < 4; q++) {
        CP_ASYNC16(sA0 + q * 16, aRow + q * 4);
        CP_ASYNC16(sB0 + q * 16, bRow + q * 4);
    }
    CP_COMMIT();

    for (int ch = 0; ch < NCH; ch++) {
        const int buf = ch & 1;
        if (ch + 1 < NCH) {
            const int k1 = (ch + 1) * 32;
            const uint32_t dA = sA0 + (buf ^ 1) * (2 * TILEW * 4);
            const uint32_t dB = sB0 + (buf ^ 1) * (2 * TILEW * 4);
            #pragma unroll
            for (int q = 0; q < 4; q++) {
                CP_ASYNC16(dA + q * 16, aRow + k1 + q * 4);
                CP_ASYNC16(dB + q * 16, bRow + k1 + q * 4);
            }
            CP_COMMIT();
            CP_WAIT1();
        } else {
            CP_WAIT0();
        }
        __syncthreads();

        const uint32_t* as = sm + buf * 2 * TILEW;
        const uint32_t* bs = as + TILEW;
        #pragma unroll
        for (int g = 0; g < 4; g++) {
            const int kk = g * 8;
            uint32_t b[4][2];
            #pragma unroll
            for (int ni = 0; ni < 4; ni++) {
                const int base = (warp_n * 32 + ni * 8 + l4) * LDS_S + kk + lm;
                b[ni][0] = bs[base];
                b[ni][1] = bs[base + 4];
            }
            #pragma unroll
            for (int mi = 0; mi < 4; mi++) {
                const int base = (warp_m * 64 + mi * 16 + l4) * LDS_S + kk + lm;
                uint32_t a[4];
                a[0] = as[base];
                a[1] = as[base + 8 * LDS_S];
                a[2] = as[base + 4];
                a[3] = as[base + 8 * LDS_S + 4];
                #pragma unroll
                for (int ni = 0; ni < 4; ni++) mma_tf32(acc[mi][ni], a, b[ni]);
            }
        }
        __syncthreads();
    }

    float* Cb = C + (size_t)bt * strideC;
    if (EPI == 0) {
        #pragma unroll
        for (int mi = 0; mi < 4; mi++) {
            const int gr = m0 + warp_m * 64 + mi * 16 + l4;
            const float bv0 = bias[gr], bv8 = bias[gr + 8];
            #pragma unroll
            for (int ni = 0; ni < 4; ni++) {
                const int gc = n0 + warp_n * 32 + ni * 8 + lm * 2;
                float2 o0 = { tf32f(acc[mi][ni][0] + bv0), tf32f(acc[mi][ni][1] + bv0) };
                float2 o1 = { tf32f(acc[mi][ni][2] + bv8), tf32f(acc[mi][ni][3] + bv8) };
                *reinterpret_cast<float2*>(&Cb[(size_t)gr * ldc + gc]) = o0;
                *reinterpret_cast<float2*>(&Cb[(size_t)(gr + 8) * ldc + gc]) = o1;
            }
        }
    } else {
        const float g = __ldg(gamma);
        const float* Xb = Xres + (size_t)bt * CF * NP;
        #pragma unroll
        for (int mi = 0; mi < 4; mi++) {
            const int gr = m0 + warp_m * 64 + mi * 16 + l4;
            #pragma unroll
            for (int ni = 0; ni < 4; ni++) {
                const int gc = n0 + warp_n * 32 + ni * 8 + lm * 2;
                if (gc < NTOK)
                    Cb[(size_t)gr * ldc + gc] = g * acc[mi][ni][0] + Xb[(size_t)gr * NP + gc];
                if (gc + 1 < NTOK)
                    Cb[(size_t)gr * ldc + gc + 1] = g * acc[mi][ni][1] + Xb[(size_t)gr * NP + gc + 1];
                if (gc < NTOK)
                    Cb[(size_t)(gr + 8) * ldc + gc] = g * acc[mi][ni][2] + Xb[(size_t)(gr + 8) * NP + gc];
                if (gc + 1 < NTOK)
                    Cb[(size_t)(gr + 8) * ldc + gc + 1] = g * acc[mi][ni][3] + Xb[(size_t)(gr + 8) * NP + gc + 1];
            }
        }
    }
}

// ---------------------------------------------------------------------------
// 4) SPLIT=3 GEMM on PRE-SPLIT operands: pure LDS+MMA mainloop, chunk 16,
//    stride 20 (conflict-free), 2-stage cp.async, 2 CTAs/SM.
//    EPI 2: fused q/k projection (blockIdx.y selects); writes Ch/Cl pre-split
//    EPI 3: raw scores
// ---------------------------------------------------------------------------
template <int EPI>
__global__ __launch_bounds__(256, 2)
void gemm_s3p_kernel(const float* __restrict__ Ah, const float* __restrict__ Al,
                     int lda, size_t strideA,
                     const float* __restrict__ Bh, const float* __restrict__ Bl,
                     const float* __restrict__ B2h, const float* __restrict__ B2l,
                     int ldb, size_t strideB,
                     int K,
                     const float* __restrict__ bias, const float* __restrict__ bias2,
                     float* __restrict__ Ch, float* __restrict__ Cl,
                     float* __restrict__ C2h, float* __restrict__ C2l,
                     int ldc, size_t strideC) {
    extern __shared__ uint32_t sm[];
    const uint32_t smem_base = smem_u32(sm);

    const int bt = blockIdx.z;
    const int m0 = blockIdx.x * 128;
    int n0;
    const float *Bhs, *Bls, *biassel;
    float *Chs, *Cls;
    if (EPI == 2) {
        n0 = 0;
        const bool alt = (blockIdx.y != 0);
        Bhs = alt ? B2h : Bh;  Bls = alt ? B2l : Bl;
        biassel = alt ? bias2 : bias;
        Chs = alt ? C2h : Ch;  Cls = alt ? C2l : Cl;
    } else {
        n0 = blockIdx.y * 128;
        Bhs = Bh; Bls = Bl; biassel = bias; Chs = Ch; Cls = Cl;
    }

    const float* Ahb = Ah  + (size_t)bt * strideA + (size_t)m0 * lda;
    const float* Alb = Al  + (size_t)bt * strideA + (size_t)m0 * lda;
    const float* Bhb = Bhs + (size_t)bt * strideB + (size_t)n0 * ldb;
    const float* Blb = Bls + (size_t)bt * strideB + (size_t)n0 * ldb;

    const int t = threadIdx.x;
    const int wid = t >> 5, lane = t & 31;
    const int wm = wid & 1, wn = wid >> 1;
    const int l4 = lane >> 2, lm = lane & 3;

    // producer: tile = t>>6 (0:Ah 1:Al 2:Bh 3:Bl), 2 rows each, 4 granules/row... 
    // rows are 16 floats = 4 granules; thread covers rows 2*local .. 2*local+1.
    const int ptile = t >> 6, plocal = t & 63;
    const float* tsrc = (ptile == 0) ? Ahb : (ptile == 1) ? Alb : (ptile == 2) ? Bhb : Blb;
    const int pld = (ptile < 2) ? lda : ldb;
    const int pr0 = plocal * 2;
    const uint32_t pDst0 = smem_base + (uint32_t)((ptile * T3 + pr0 * S3) * 4);

    float acc[4][4][4];
    #pragma unroll
    for (int mi = 0; mi < 4; mi++)
        #pragma unroll
        for (int ni = 0; ni < 4; ni++)
            #pragma unroll
            for (int r = 0; r < 4; r++) acc[mi][ni][r] = 0.0f;

    const int NCH = K / 16;

    #define S3P_ISSUE(stg, koff) do {                                          \
        const uint32_t _d = pDst0 + (uint32_t)(stg) * (STG3 * 4);              \
        _Pragma("unroll")                                                      \
        for (int i = 0; i < 8; i++) {                                          \
            const int rr = i >> 2, q = i & 3;                                  \
            CP_ASYNC16(_d + (rr * S3 * 4) + q * 16,                            \
                       tsrc + (size_t)(pr0 + rr) * pld + (koff) + q * 4);      \
        }                                                                      \
        CP_COMMIT();                                                           \
    } while (0)

    S3P_ISSUE(0, 0);

    for (int ch = 0; ch < NCH; ch++) {
        const int buf = ch & 1;
        if (ch + 1 < NCH) {
            S3P_ISSUE(buf ^ 1, (ch + 1) * 16);
            CP_WAIT1();
        } else {
            CP_WAIT0();
        }
        __syncthreads();

        const uint32_t* ahs = sm + buf * STG3;
        const uint32_t* als = ahs + T3;
        const uint32_t* bhs = ahs + 2 * T3;
        const uint32_t* bls = ahs + 3 * T3;
        #pragma unroll
        for (int g = 0; g < 2; g++) {
            const int kk = g * 8;
            uint32_t bh[4][2], bl[4][2];
            #pragma unroll
            for (int ni = 0; ni < 4; ni++) {
                const int ro = (wn * 32 + ni * 8 + l4) * S3 + kk + lm;
                bh[ni][0] = bhs[ro];  bh[ni][1] = bhs[ro + 4];
                bl[ni][0] = bls[ro];  bl[ni][1] = bls[ro + 4];
            }
            #pragma unroll
            for (int mi = 0; mi < 4; mi++) {
                const int ro = (wm * 64 + mi * 16 + l4) * S3 + kk + lm;
                uint32_t ah_[4], al_[4];
                ah_[0] = ahs[ro];               al_[0] = als[ro];
                ah_[1] = ahs[ro + 8 * S3];      al_[1] = als[ro + 8 * S3];
                ah_[2] = ahs[ro + 4];           al_[2] = als[ro + 4];
                ah_[3] = ahs[ro + 8 * S3 + 4];  al_[3] = als[ro + 8 * S3 + 4];
                #pragma unroll
                for (int ni = 0; ni < 4; ni++) {
                    mma_tf32(acc[mi][ni], ah_, bl[ni]);
                    mma_tf32(acc[mi][ni], al_, bh[ni]);
                    mma_tf32(acc[mi][ni], ah_, bh[ni]);
                }
            }
        }
        __syncthreads();
    }
    #undef S3P_ISSUE

    if (EPI == 2) {
        float* Cbh = Chs + (size_t)bt * strideC;
        float* Cbl = Cls + (size_t)bt * strideC;
        #pragma unroll
        for (int mi = 0; mi < 4; mi++) {
            const int gr = m0 + wm * 64 + mi * 16 + l4;
            #pragma unroll
            for (int ni = 0; ni < 4; ni++) {
                const int gc = n0 + wn * 32 + ni * 8 + lm * 2;
                const float b0 = biassel[gc], b1 = biassel[gc + 1];
                const float v00 = acc[mi][ni][0] + b0, v01 = acc[mi][ni][1] + b1;
                const float v10 = acc[mi][ni][2] + b0, v11 = acc[mi][ni][3] + b1;
                const float h00 = tf32f(v00), h01 = tf32f(v01);
                const float h10 = tf32f(v10), h11 = tf32f(v11);
                float2 oh0 = { h00, h01 }, oh1 = { h10, h11 };
                float2 ol0 = { tf32f(v00 - h00), tf32f(v01 - h01) };
                float2 ol1 = { tf32f(v10 - h10), tf32f(v11 - h11) };
                *reinterpret_cast<float2*>(&Cbh[(size_t)gr * ldc + gc]) = oh0;
                *reinterpret_cast<float2*>(&Cbh[(size_t)(gr + 8) * ldc + gc]) = oh1;
                *reinterpret_cast<float2*>(&Cbl[(size_t)gr * ldc + gc]) = ol0;
                *reinterpret_cast<float2*>(&Cbl[(size_t)(gr + 8) * ldc + gc]) = ol1;
            }
        }
    } else {
        float* Cb = Ch + (size_t)bt * strideC;
        #pragma unroll
        for (int mi = 0; mi < 4; mi++) {
            const int gr = m0 + wm * 64 + mi * 16 + l4;
            #pragma unroll
            for (int ni = 0; ni < 4; ni++) {
                const int gc = n0 + wn * 32 + ni * 8 + lm * 2;
                float2 o0 = { acc[mi][ni][0], acc[mi][ni][1] };
                float2 o1 = { acc[mi][ni][2], acc[mi][ni][3] };
                *reinterpret_cast<float2*>(&Cb[(size_t)gr * ldc + gc]) = o0;
                *reinterpret_cast<float2*>(&Cb[(size_t)(gr + 8) * ldc + gc]) = o1;
            }
        }
    }
}

// ---------------------------------------------------------------------------
// Launch
// ---------------------------------------------------------------------------
extern "C" void kernel_launch(void* const* d_in, const int* in_sizes, int n_in,
                              void* d_out, int out_size) {
    const float* img   = (const float*)d_in[0];
    const float* tac   = (const float*)d_in[1];
    const float* Wq    = (const float*)d_in[2];
    const float* bq    = (const float*)d_in[3];
    const float* Wk    = (const float*)d_in[4];
    const float* bk    = (const float*)d_in[5];
    const float* Wv    = (const float*)d_in[6];
    const float* bv    = (const float*)d_in[7];
    const float* gamma = (const float*)d_in[8];
    float* out = (float*)d_out;

    float *gX, *gXTh, *gXTl, *gWvh, *gWqh, *gWql, *gWkh, *gWkl;
    float *gQTh, *gQTl, *gKTh, *gKTl, *gV, *gA;
    cudaGetSymbolAddress((void**)&gX,   g_X);
    cudaGetSymbolAddress((void**)&gXTh, g_XTh);
    cudaGetSymbolAddress((void**)&gXTl, g_XTl);
    cudaGetSymbolAddress((void**)&gWvh, g_Wvh);
    cudaGetSymbolAddress((void**)&gWqh, g_Wqh);
    cudaGetSymbolAddress((void**)&gWql, g_Wql);
    cudaGetSymbolAddress((void**)&gWkh, g_Wkh);
    cudaGetSymbolAddress((void**)&gWkl, g_Wkl);
    cudaGetSymbolAddress((void**)&gQTh, g_QTh);
    cudaGetSymbolAddress((void**)&gQTl, g_QTl);
    cudaGetSymbolAddress((void**)&gKTh, g_KTh);
    cudaGetSymbolAddress((void**)&gKTl, g_KTl);
    cudaGetSymbolAddress((void**)&gV,   g_V);
    cudaGetSymbolAddress((void**)&gA,   g_ATT);

    cudaFuncSetAttribute(gemm_async_kernel<0>, cudaFuncAttributeMaxDynamicSharedMemorySize, SMEM_T);
    cudaFuncSetAttribute(gemm_async_kernel<1>, cudaFuncAttributeMaxDynamicSharedMemorySize, SMEM_T);
    cudaFuncSetAttribute(gemm_s3p_kernel<2>,   cudaFuncAttributeMaxDynamicSharedMemorySize, SMEM_3);
    cudaFuncSetAttribute(gemm_s3p_kernel<3>,   cudaFuncAttributeMaxDynamicSharedMemorySize, SMEM_3);

    // 1) residual + XT hi/lo + weight prep
    build_x_kernel <<<dim3((NP + 255) / 256, CF, BT), 256>>>(img, tac);
    build_xt_kernel<<<dim3(CF / 256, NP, BT), 256>>>(img, tac);
    prep_round_kernel<<<(CF * CF + 255) / 256, 256>>>(Wv, gWvh, CF * CF);
    prep_split_kernel<<<(CQ * CF + 255) / 256, 256>>>(Wq, gWqh, gWql, CQ * CF);
    prep_split_kernel<<<(CQ * CF + 255) / 256, 256>>>(Wk, gWkh, gWkl, CQ * CF);

    // 2) fused q+k projections (3xTF32, pre-split operands, no cvt in loop)
    gemm_s3p_kernel<2><<<dim3(NP / 128, 2, BT), 256, SMEM_3>>>(
        gXTh, gXTl, CF, (size_t)NP * CF,
        gWqh, gWql, gWkh, gWkl, CF, 0,
        CF, bq, bk,
        gQTh, gQTl, gKTh, gKTl, CQ, (size_t)NP * CQ);

    // 3) v projection (pre-rounded operands)
    gemm_async_kernel<0><<<dim3(CF / 128, NP / 128, BT), 256, SMEM_T>>>(
        gWvh, CF, 0,
        gXTh, CF, (size_t)NP * CF,
        CF, bv, nullptr, nullptr,
        gV, NP, (size_t)CF * NP);

    // 4) attention scores (3xTF32, pre-split q/k)
    gemm_s3p_kernel<3><<<dim3(NP / 128, NP / 128, BT), 256, SMEM_3>>>(
        gQTh, gQTl, CQ, (size_t)NP * CQ,
        gKTh, gKTl, nullptr, nullptr, CQ, (size_t)NP * CQ,
        CQ, nullptr, nullptr,
        gA, nullptr, nullptr, nullptr, NP, (size_t)NP * NP);

    // 5) softmax -> tf32-rounded probs
    softmax_kernel<<<dim3(NTOK, BT), 256>>>();

    // 6) out = gamma * (V @ P^T) + X
    gemm_async_kernel<1><<<dim3(CF / 128, NP / 128, BT), 256, SMEM_T>>>(
        gV, NP, (size_t)CF * NP,
        gA, NP, (size_t)NP * NP,
        NP, nullptr, gamma, gX,
        out, NTOK, (size_t)CF * NTOK);
}

// round 14
// speedup vs baseline: 1.1042x; 1.1042x over previous
#include <cuda_runtime.h>
#include <cstdint>

// ---------------------------------------------------------------------------
// Shapes
// ---------------------------------------------------------------------------
#define BT   12
#define CF   1024
#define CQ   128
#define NTOK 2401
#define NP   2432
#define HF   49

// ---------------------------------------------------------------------------
// Scratch
// ---------------------------------------------------------------------------
__device__ float g_XT [(size_t)BT * NP * CF];   // raw XT (q/k path)
__device__ float g_XTh[(size_t)BT * NP * CF];   // tf32-rounded XT (v path)
__device__ float g_Wvh[(size_t)CF * CF];        // tf32-rounded Wv
__device__ float g_QT [(size_t)BT * NP * CQ];   // raw q
__device__ float g_KT [(size_t)BT * NP * CQ];   // raw k
__device__ float g_V  [(size_t)BT * CF * NP];   // tf32-rounded v (incl bias)
__device__ float g_ATT[(size_t)BT * NP * NP];   // raw scores -> tf32-rounded probs

__device__ __forceinline__ uint32_t f2tf(float f) {
    uint32_t u; asm("cvt.rna.tf32.f32 %0, %1;" : "=r"(u) : "f"(f)); return u;
}
__device__ __forceinline__ float tf32f(float f) { return __uint_as_float(f2tf(f)); }
__device__ __forceinline__ uint32_t u2tf(uint32_t x) {
    uint32_t u; asm("cvt.rna.tf32.f32 %0, %1;" : "=r"(u) : "f"(__uint_as_float(x))); return u;
}
__device__ __forceinline__ uint32_t smem_u32(const void* p) {
    uint32_t a;
    asm("{ .reg .u64 t; cvta.to.shared.u64 t, %1; cvt.u32.u64 %0, t; }" : "=r"(a) : "l"(p));
    return a;
}

// residual gather: x[bt][c][n] straight from inputs (L2-resident)
__device__ __forceinline__ float gather_x(const float* __restrict__ img,
                                          const float* __restrict__ tac,
                                          int bt, int c, int n) {
    int i = n / HF, j = n % HF;
    return (c < 512)
        ? tac[(((size_t)bt * 512 + c) * 7 + (i / 7)) * 7 + (j / 7)]
        : img[(((size_t)bt * 512 + (c - 512)) * 7 + (i % 7)) * 7 + (j % 7)];
}

__device__ __forceinline__ void mma_tf32(float c[4], const uint32_t a[4], const uint32_t b[2]) {
    asm volatile(
        "mma.sync.aligned.m16n8k8.row.col.f32.tf32.tf32.f32 "
        "{%0,%1,%2,%3}, {%4,%5,%6,%7}, {%8,%9}, {%0,%1,%2,%3};"
        : "+f"(c[0]), "+f"(c[1]), "+f"(c[2]), "+f"(c[3])
        : "r"(a[0]), "r"(a[1]), "r"(a[2]), "r"(a[3]), "r"(b[0]), "r"(b[1]));
}

#define CP_ASYNC16(dst_u32, src_ptr) \
    asm volatile("cp.async.cg.shared.global [%0], [%1], 16;" :: "r"(dst_u32), "l"(src_ptr) : "memory")
#define CP_COMMIT() asm volatile("cp.async.commit_group;" ::: "memory")
#define CP_WAIT0()  asm volatile("cp.async.wait_group 0;" ::: "memory")
#define CP_WAIT1()  asm volatile("cp.async.wait_group 1;" ::: "memory")

// ---------------------------------------------------------------------------
// 1) XT raw + rounded (zero rows for n >= NTOK)
// ---------------------------------------------------------------------------
__global__ void build_xt_kernel(const float* __restrict__ img,
                                const float* __restrict__ tac) {
    int c = blockIdx.x * 256 + threadIdx.x;
    int n = blockIdx.y, bt = blockIdx.z;
    if (c >= CF) return;
    float v = 0.0f;
    if (n < NTOK) v = gather_x(img, tac, bt, c, n);
    size_t base = ((size_t)bt * NP + n) * CF + c;
    g_XT[base]  = v;
    g_XTh[base] = tf32f(v);
}

// ---------------------------------------------------------------------------
// 1b) Wv -> rounded
// ---------------------------------------------------------------------------
__global__ void prep_round_kernel(const float* __restrict__ src,
                                  float* __restrict__ dst, int n) {
    int i = blockIdx.x * 256 + threadIdx.x;
    if (i < n) dst[i] = tf32f(src[i]);
}

// ---------------------------------------------------------------------------
// 2) row softmax (m < 2401), writes tf32-rounded probs, zeroes padding
// ---------------------------------------------------------------------------
__global__ __launch_bounds__(256)
void softmax_kernel() {
    __shared__ float row[NTOK];
    __shared__ float red[256];
    const int n = blockIdx.x, bt = blockIdx.y;
    float* base = g_ATT + ((size_t)bt * NP + n) * NP;
    const int t = threadIdx.x;

    float mx = -1e30f;
    for (int m = t; m < NTOK; m += 256) { float v = base[m]; row[m] = v; mx = fmaxf(mx, v); }
    red[t] = mx; __syncthreads();
    for (int s = 128; s > 0; s >>= 1) { if (t < s) red[t] = fmaxf(red[t], red[t + s]); __syncthreads(); }
    mx = red[0]; __syncthreads();

    float sum = 0.0f;
    for (int m = t; m < NTOK; m += 256) { float e = __expf(row[m] - mx); row[m] = e; sum += e; }
    red[t] = sum; __syncthreads();
    for (int s = 128; s > 0; s >>= 1) { if (t < s) red[t] += red[t + s]; __syncthreads(); }
    float inv = 1.0f / red[0];

    for (int m = t; m < NTOK; m += 256) base[m] = tf32f(row[m] * inv);
    for (int m = NTOK + t; m < NP; m += 256) base[m] = 0.0f;
}

// ---------------------------------------------------------------------------
// Shared tiling constants (stride-36 layout, conflict-free scalar LDS)
// ---------------------------------------------------------------------------
#define LDS_S 36
#define TILEW (128 * LDS_S)            // words per 128x32 tile
#define SMEM_T (4 * TILEW * 4)         // 73728 B double buffer

// ---------------------------------------------------------------------------
// 3) SPLIT=1 GEMM on PRE-ROUNDED operands: pure LDS+MMA mainloop (no cvt).
//    C[M,N] = A[M,K] @ B[N,K]^T (both K-major). 256 thr (8 warps 2Mx4N,
//    warp tile 64x32), chunk 32, 2-stage cp.async, 2 CTAs/SM.
//    EPI 0: C = tf32f(acc + bias[row])                (v writeback)
//    EPI 1: C = gamma*acc + gather_x(row,col), col<NTOK  (final output)
// ---------------------------------------------------------------------------
template <int EPI>
__global__ __launch_bounds__(256, 2)
void gemm_async_kernel(const float* __restrict__ A, int lda, size_t strideA,
                       const float* __restrict__ B, int ldb, size_t strideB,
                       int K,
                       const float* __restrict__ bias,
                       const float* __restrict__ gamma,
                       const float* __restrict__ img,
                       const float* __restrict__ tac,
                       float* __restrict__ C, int ldc, size_t strideC) {
    extern __shared__ uint32_t sm[];
    const uint32_t smem_base = smem_u32(sm);

    const int bt = blockIdx.z;
    const int m0 = blockIdx.x * 128;
    const int n0 = blockIdx.y * 128;
    const float* Ab = A + (size_t)bt * strideA + (size_t)m0 * lda;
    const float* Bb = B + (size_t)bt * strideB + (size_t)n0 * ldb;

    const int t = threadIdx.x;
    const int wid = t >> 5, lane = t & 31;
    const int warp_m = wid & 1, warp_n = wid >> 1;
    const int l4 = lane >> 2, lm = lane & 3;

    const int prow = t >> 1;
    const int pcol = (t & 1) * 16;
    const float* aRow = Ab + (size_t)prow * lda + pcol;
    const float* bRow = Bb + (size_t)prow * ldb + pcol;
    const uint32_t sA0 = smem_base + (prow * LDS_S + pcol) * 4;
    const uint32_t sB0 = sA0 + TILEW * 4;

    float acc[4][4][4];
    #pragma unroll
    for (int mi = 0; mi < 4; mi++)
        #pragma unroll
        for (int ni = 0; ni < 4; ni++)
            #pragma unroll
            for (int r = 0; r < 4; r++) acc[mi][ni][r] = 0.0f;

    const int NCH = K / 32;

    #pragma unroll
    for (int q = 0; q < 4; q++) {
        CP_ASYNC16(sA0 + q * 16, aRow + q * 4);
        CP_ASYNC16(sB0 + q * 16, bRow + q * 4);
    }
    CP_COMMIT();

    for (int ch = 0; ch < NCH; ch++) {
        const int buf = ch & 1;
        if (ch + 1 < NCH) {
            const int k1 = (ch + 1) * 32;
            const uint32_t dA = sA0 + (buf ^ 1) * (2 * TILEW * 4);
            const uint32_t dB = sB0 + (buf ^ 1) * (2 * TILEW * 4);
            #pragma unroll
            for (int q = 0; q < 4; q++) {
                CP_ASYNC16(dA + q * 16, aRow + k1 + q * 4);
                CP_ASYNC16(dB + q * 16, bRow + k1 + q * 4);
            }
            CP_COMMIT();
            CP_WAIT1();
        } else {
            CP_WAIT0();
        }
        __syncthreads();

        const uint32_t* as = sm + buf * 2 * TILEW;
        const uint32_t* bs = as + TILEW;
        #pragma unroll
        for (int g = 0; g < 4; g++) {
            const int kk = g * 8;
            uint32_t b[4][2];
            #pragma unroll
            for (int ni = 0; ni < 4; ni++) {
                const int base = (warp_n * 32 + ni * 8 + l4) * LDS_S + kk + lm;
                b[ni][0] = bs[base];
                b[ni][1] = bs[base + 4];
            }
            #pragma unroll
            for (int mi = 0; mi < 4; mi++) {
                const int base = (warp_m * 64 + mi * 16 + l4) * LDS_S + kk + lm;
                uint32_t a[4];
                a[0] = as[base];
                a[1] = as[base + 8 * LDS_S];
                a[2] = as[base + 4];
                a[3] = as[base + 8 * LDS_S + 4];
                #pragma unroll
                for (int ni = 0; ni < 4; ni++) mma_tf32(acc[mi][ni], a, b[ni]);
            }
        }
        __syncthreads();
    }

    float* Cb = C + (size_t)bt * strideC;
    if (EPI == 0) {
        #pragma unroll
        for (int mi = 0; mi < 4; mi++) {
            const int gr = m0 + warp_m * 64 + mi * 16 + l4;
            const float bv0 = bias[gr], bv8 = bias[gr + 8];
            #pragma unroll
            for (int ni = 0; ni < 4; ni++) {
                const int gc = n0 + warp_n * 32 + ni * 8 + lm * 2;
                float2 o0 = { tf32f(acc[mi][ni][0] + bv0), tf32f(acc[mi][ni][1] + bv0) };
                float2 o1 = { tf32f(acc[mi][ni][2] + bv8), tf32f(acc[mi][ni][3] + bv8) };
                *reinterpret_cast<float2*>(&Cb[(size_t)gr * ldc + gc]) = o0;
                *reinterpret_cast<float2*>(&Cb[(size_t)(gr + 8) * ldc + gc]) = o1;
            }
        }
    } else {
        const float g = __ldg(gamma);
        #pragma unroll
        for (int mi = 0; mi < 4; mi++) {
            const int gr = m0 + warp_m * 64 + mi * 16 + l4;
            #pragma unroll
            for (int ni = 0; ni < 4; ni++) {
                const int gc = n0 + warp_n * 32 + ni * 8 + lm * 2;
                if (gc < NTOK)
                    Cb[(size_t)gr * ldc + gc] =
                        g * acc[mi][ni][0] + gather_x(img, tac, bt, gr, gc);
                if (gc + 1 < NTOK)
                    Cb[(size_t)gr * ldc + gc + 1] =
                        g * acc[mi][ni][1] + gather_x(img, tac, bt, gr, gc + 1);
                if (gc < NTOK)
                    Cb[(size_t)(gr + 8) * ldc + gc] =
                        g * acc[mi][ni][2] + gather_x(img, tac, bt, gr + 8, gc);
                if (gc + 1 < NTOK)
                    Cb[(size_t)(gr + 8) * ldc + gc + 1] =
                        g * acc[mi][ni][3] + gather_x(img, tac, bt, gr + 8, gc + 1);
            }
        }
    }
}

// ---------------------------------------------------------------------------
// 4) SPLIT=3 (3xTF32) GEMM — R12 form, unchanged: cp.async double-buffered raw
//    staging, hi/lo split on consume, chunk 32, 256 threads, 2 CTAs/SM.
//    EPI 2: fused q/k projection (blockIdx.y selects B/bias/C), C = acc + bias[col]
//    EPI 3: C = acc (raw scores)
// ---------------------------------------------------------------------------
template <int EPI>
__global__ __launch_bounds__(256, 2)
void gemm_async3_kernel(const float* __restrict__ A, int lda, size_t strideA,
                        const float* __restrict__ B, int ldb, size_t strideB,
                        const float* __restrict__ B2,
                        int K,
                        const float* __restrict__ bias,
                        const float* __restrict__ bias2,
                        float* __restrict__ C, int ldc, size_t strideC,
                        float* __restrict__ C2) {
    extern __shared__ uint32_t sm[];
    const uint32_t smem_base = smem_u32(sm);

    const int bt = blockIdx.z;
    const int m0 = blockIdx.x * 128;
    int n0;
    const float* Bsel;
    const float* biassel;
    float* Csel;
    if (EPI == 2) {
        n0 = 0;
        const bool alt = (blockIdx.y != 0);
        Bsel = alt ? B2 : B;
        biassel = alt ? bias2 : bias;
        Csel = alt ? C2 : C;
    } else {
        n0 = blockIdx.y * 128;
        Bsel = B; biassel = bias; Csel = C;
    }

    const float* Ab = A + (size_t)bt * strideA + (size_t)m0 * lda;
    const float* Bb = Bsel + (size_t)bt * strideB + (size_t)n0 * ldb;

    const int t = threadIdx.x;
    const int wid = t >> 5, lane = t & 31;
    const int warp_m = wid & 1, warp_n = wid >> 1;
    const int l4 = lane >> 2, lm = lane & 3;

    const int prow = t >> 1;
    const int pcol = (t & 1) * 16;
    const float* aRow = Ab + (size_t)prow * lda + pcol;
    const float* bRow = Bb + (size_t)prow * ldb + pcol;
    const uint32_t sA0 = smem_base + (prow * LDS_S + pcol) * 4;
    const uint32_t sB0 = sA0 + TILEW * 4;

    float acc[4][4][4];
    #pragma unroll
    for (int mi = 0; mi < 4; mi++)
        #pragma unroll
        for (int ni = 0; ni < 4; ni++)
            #pragma unroll
            for (int r = 0; r < 4; r++) acc[mi][ni][r] = 0.0f;

    const int NCH = K / 32;

    #pragma unroll
    for (int q = 0; q < 4; q++) {
        CP_ASYNC16(sA0 + q * 16, aRow + q * 4);
        CP_ASYNC16(sB0 + q * 16, bRow + q * 4);
    }
    CP_COMMIT();

    for (int ch = 0; ch < NCH; ch++) {
        const int buf = ch & 1;
        if (ch + 1 < NCH) {
            const int k1 = (ch + 1) * 32;
            const uint32_t dA = sA0 + (buf ^ 1) * (2 * TILEW * 4);
            const uint32_t dB = sB0 + (buf ^ 1) * (2 * TILEW * 4);
            #pragma unroll
            for (int q = 0; q < 4; q++) {
                CP_ASYNC16(dA + q * 16, aRow + k1 + q * 4);
                CP_ASYNC16(dB + q * 16, bRow + k1 + q * 4);
            }
            CP_COMMIT();
            CP_WAIT1();
        } else {
            CP_WAIT0();
        }
        __syncthreads();

        const uint32_t* as = sm + buf * 2 * TILEW;
        const uint32_t* bs = as + TILEW;
        #pragma unroll
        for (int g = 0; g < 4; g++) {
            const int kk = g * 8;
            uint32_t bh[4][2], bl[4][2];
            #pragma unroll
            for (int ni = 0; ni < 4; ni++) {
                const int base = (warp_n * 32 + ni * 8 + l4) * LDS_S + kk + lm;
                const uint32_t r0 = bs[base], r1 = bs[base + 4];
                bh[ni][0] = u2tf(r0);
                bl[ni][0] = f2tf(__uint_as_float(r0) - __uint_as_float(bh[ni][0]));
                bh[ni][1] = u2tf(r1);
                bl[ni][1] = f2tf(__uint_as_float(r1) - __uint_as_float(bh[ni][1]));
            }
            #pragma unroll
            for (int mi = 0; mi < 4; mi++) {
                const int base = (warp_m * 64 + mi * 16 + l4) * LDS_S + kk + lm;
                uint32_t ar[4];
                ar[0] = as[base];
                ar[1] = as[base + 8 * LDS_S];
                ar[2] = as[base + 4];
                ar[3] = as[base + 8 * LDS_S + 4];
                uint32_t ah[4], al[4];
                #pragma unroll
                for (int r = 0; r < 4; r++) {
                    ah[r] = u2tf(ar[r]);
                    al[r] = f2tf(__uint_as_float(ar[r]) - __uint_as_float(ah[r]));
                }
                #pragma unroll
                for (int ni = 0; ni < 4; ni++) {
                    mma_tf32(acc[mi][ni], ah, bl[ni]);
                    mma_tf32(acc[mi][ni], al, bh[ni]);
                    mma_tf32(acc[mi][ni], ah, bh[ni]);
                }
            }
        }
        __syncthreads();
    }

    float* Cb = Csel + (size_t)bt * strideC;
    if (EPI == 2) {
        #pragma unroll
        for (int mi = 0; mi < 4; mi++) {
            const int gr = m0 + warp_m * 64 + mi * 16 + l4;
            #pragma unroll
            for (int ni = 0; ni < 4; ni++) {
                const int gc = n0 + warp_n * 32 + ni * 8 + lm * 2;
                const float b0 = biassel[gc], b1 = biassel[gc + 1];
                float2 o0 = { acc[mi][ni][0] + b0, acc[mi][ni][1] + b1 };
                float2 o1 = { acc[mi][ni][2] + b0, acc[mi][ni][3] + b1 };
                *reinterpret_cast<float2*>(&Cb[(size_t)gr * ldc + gc]) = o0;
                *reinterpret_cast<float2*>(&Cb[(size_t)(gr + 8) * ldc + gc]) = o1;
            }
        }
    } else {
        #pragma unroll
        for (int mi = 0; mi < 4; mi++) {
            const int gr = m0 + warp_m * 64 + mi * 16 + l4;
            #pragma unroll
            for (int ni = 0; ni < 4; ni++) {
                const int gc = n0 + warp_n * 32 + ni * 8 + lm * 2;
                float2 o0 = { acc[mi][ni][0], acc[mi][ni][1] };
                float2 o1 = { acc[mi][ni][2], acc[mi][ni][3] };
                *reinterpret_cast<float2*>(&Cb[(size_t)gr * ldc + gc]) = o0;
                *reinterpret_cast<float2*>(&Cb[(size_t)(gr + 8) * ldc + gc]) = o1;
            }
        }
    }
}

// ---------------------------------------------------------------------------
// Launch
// ---------------------------------------------------------------------------
extern "C" void kernel_launch(void* const* d_in, const int* in_sizes, int n_in,
                              void* d_out, int out_size) {
    const float* img   = (const float*)d_in[0];
    const float* tac   = (const float*)d_in[1];
    const float* Wq    = (const float*)d_in[2];
    const float* bq    = (const float*)d_in[3];
    const float* Wk    = (const float*)d_in[4];
    const float* bk    = (const float*)d_in[5];
    const float* Wv    = (const float*)d_in[6];
    const float* bv    = (const float*)d_in[7];
    const float* gamma = (const float*)d_in[8];
    float* out = (float*)d_out;

    float *gXT, *gXTh, *gWvh, *gQT, *gKT, *gV, *gA;
    cudaGetSymbolAddress((void**)&gXT,  g_XT);
    cudaGetSymbolAddress((void**)&gXTh, g_XTh);
    cudaGetSymbolAddress((void**)&gWvh, g_Wvh);
    cudaGetSymbolAddress((void**)&gQT,  g_QT);
    cudaGetSymbolAddress((void**)&gKT,  g_KT);
    cudaGetSymbolAddress((void**)&gV,   g_V);
    cudaGetSymbolAddress((void**)&gA,   g_ATT);

    cudaFuncSetAttribute(gemm_async_kernel<0>,  cudaFuncAttributeMaxDynamicSharedMemorySize, SMEM_T);
    cudaFuncSetAttribute(gemm_async_kernel<1>,  cudaFuncAttributeMaxDynamicSharedMemorySize, SMEM_T);
    cudaFuncSetAttribute(gemm_async3_kernel<2>, cudaFuncAttributeMaxDynamicSharedMemorySize, SMEM_T);
    cudaFuncSetAttribute(gemm_async3_kernel<3>, cudaFuncAttributeMaxDynamicSharedMemorySize, SMEM_T);

    // 1) XT (raw + rounded) + rounded Wv  (no g_X buffer — gathered in epilogue)
    build_xt_kernel<<<dim3(CF / 256, NP, BT), 256>>>(img, tac);
    prep_round_kernel<<<(CF * CF + 255) / 256, 256>>>(Wv, gWvh, CF * CF);

    // 2) fused q+k projections (3xTF32, raw operands, split on consume)
    gemm_async3_kernel<2><<<dim3(NP / 128, 2, BT), 256, SMEM_T>>>(
        gXT, CF, (size_t)NP * CF,
        Wq, CF, 0, Wk,
        CF, bq, bk,
        gQT, CQ, (size_t)NP * CQ, gKT);

    // 3) v projection (pre-rounded operands, no cvt in mainloop)
    gemm_async_kernel<0><<<dim3(CF / 128, NP / 128, BT), 256, SMEM_T>>>(
        gWvh, CF, 0,
        gXTh, CF, (size_t)NP * CF,
        CF, bv, nullptr, nullptr, nullptr,
        gV, NP, (size_t)CF * NP);

    // 4) attention scores (3xTF32, raw q/k, split on consume)
    gemm_async3_kernel<3><<<dim3(NP / 128, NP / 128, BT), 256, SMEM_T>>>(
        gQT, CQ, (size_t)NP * CQ,
        gKT, CQ, (size_t)NP * CQ, nullptr,
        CQ, nullptr, nullptr,
        gA, NP, (size_t)NP * NP, nullptr);

    // 5) softmax -> tf32-rounded probs
    softmax_kernel<<<dim3(NTOK, BT), 256>>>();

    // 6) out = gamma * (V @ P^T) + gather_x (fused residual)
    gemm_async_kernel<1><<<dim3(CF / 128, NP / 128, BT), 256, SMEM_T>>>(
        gV, NP, (size_t)CF * NP,
        gA, NP, (size_t)NP * NP,
        NP, nullptr, gamma, img, tac,
        out, NTOK, (size_t)CF * NTOK);
}